// round 5
// baseline (speedup 1.0000x reference)
#include <cuda_runtime.h>
#include <math.h>

// LIANetLight hash-grid encoder.
// Inputs (metadata order):
//  0: x0      float32 [B]
//  1: y0      float32 [B]
//  2: tables  float32 [T, 2]
//  3: seeds   uint32  [L]
//  4: level_N float32 [L]
//  5: memorized_crop_size (scalar)
//  6: complete_tile_size  (scalar)
// Output: float32 [B, L*2, H, W]

#define HASH_P1 2654435761u
#define HASH_P2 805459861u
#define TW 32
#define TH 8
#define STAGE_CAP 1024

// Read a scalar that may have been stored as int32 or float32.
__device__ __forceinline__ float read_scalar_as_float(const int* p) {
    int v = *p;
    if (v > 0 && v < (1 << 24)) return (float)v;
    return __int_as_float(v);
}

// ---------------------------------------------------------------------------
// Tiled kernel: 32x8 pixel tile per CTA, 256 threads, 1 pixel/thread.
// Levels whose worst-case cell rectangle fits in STAGE_CAP are deduplicated
// through an 8KB shared-memory stage (each distinct hash cell fetched once
// per CTA); finer levels gather directly, one level at a time (4 loads in
// flight). Warp = one 32-pixel row -> fully coalesced stores.
// Requires: H % 32 == 0, T power of two.
// ---------------------------------------------------------------------------
__global__ void __launch_bounds__(256)
hashenc_tiled(const float* __restrict__ x0,
              const float* __restrict__ y0,
              const float2* __restrict__ tables,
              const unsigned int* __restrict__ seeds,
              const float* __restrict__ levelN,
              const int* __restrict__ tile_ptr,
              float* __restrict__ out,
              int H, int L, unsigned int mask)
{
    __shared__ float2 stage[STAGE_CAP];
    __shared__ float s_scale[16];
    __shared__ unsigned int s_seed[16];
    __shared__ float s_org[2];

    const int tid = threadIdx.x;
    const int b = blockIdx.z;

    if (tid < L) {
        float tf = read_scalar_as_float(tile_ptr);
        s_scale[tid] = levelN[tid] / tf;
        s_seed[tid]  = seeds[tid];
    }
    if (tid == 0) { s_org[0] = x0[b]; s_org[1] = y0[b]; }
    __syncthreads();

    const float ox = s_org[0];
    const float oy = s_org[1];
    const int tilex = blockIdx.x * TW;
    const int tiley = blockIdx.y * TH;
    const int tx = tid & 31;          // 0..31
    const int ty = tid >> 5;          // 0..7
    const int HW = H * H;
    const float px = (float)(tilex + tx) + ox;
    const float py = (float)(tiley + ty) + oy;

    float* outb = out + (size_t)b * (size_t)(2 * L) * (size_t)HW
                      + (size_t)(tiley + ty) * (size_t)H + (tilex + tx);

    for (int l = 0; l < L; l++) {
        const float sc        = s_scale[l];
        const unsigned int se = s_seed[l];

        // x interpolation terms (shared by both paths)
        const float xn  = px * sc;
        const float fxf = floorf(xn);
        const float fx  = xn - fxf;
        const int ix0   = (int)fxf;
        const float gx  = 1.0f - fx;

        const float yn  = py * sc;
        const float fyf = floorf(yn);
        const float fy  = yn - fyf;
        const int iy0   = (int)fyf;
        const float gy  = 1.0f - fy;

        // Worst-case cell rectangle for ANY 32x8 tile at this scale
        // (depends on sc only -> uniform across CTAs and warps).
        const int nxmax = (int)floorf((float)(TW - 1) * sc) + 3;
        const int nymax = (int)floorf((float)(TH - 1) * sc) + 3;
        const bool staged = (nxmax * nymax) <= STAGE_CAP;

        float2 f00, f10, f01, f11;

        if (staged) {
            // ---- staged path: each distinct cell fetched exactly once ----
            const int ixmin = (int)floorf(((float)tilex + ox) * sc);
            const int iymin = (int)floorf(((float)tiley + oy) * sc);
            const int nx = (int)floorf(((float)(tilex + TW - 1) + ox) * sc) - ixmin + 2;
            const int ny = (int)floorf(((float)(tiley + TH - 1) + oy) * sc) - iymin + 2;
            const int ncells = nx * ny;

            __syncthreads();   // previous level's consumers done with stage[]
            for (int i = tid; i < ncells; i += 256) {
                const int cy = i / nx;
                const int cx = i - cy * nx;
                const unsigned int h = ((unsigned int)(ixmin + cx) * HASH_P1)
                                     ^ ((unsigned int)(iymin + cy) * HASH_P2) ^ se;
                stage[i] = __ldg(&tables[h & mask]);
            }
            __syncthreads();

            const int base0 = (iy0 - iymin) * nx + (ix0 - ixmin);
            f00 = stage[base0];
            f10 = stage[base0 + 1];
            f01 = stage[base0 + nx];
            f11 = stage[base0 + nx + 1];
        } else {
            // ---- direct path (fine levels): 4 gathers in flight ----
            const unsigned int hx0 = (unsigned int)ix0 * HASH_P1;
            const unsigned int hx1 = hx0 + HASH_P1;   // (ix0+1)*P1 mod 2^32
            const unsigned int hy0 = (unsigned int)iy0 * HASH_P2;
            const unsigned int hy1 = hy0 + HASH_P2;
            f00 = __ldg(&tables[(hx0 ^ hy0 ^ se) & mask]);
            f10 = __ldg(&tables[(hx1 ^ hy0 ^ se) & mask]);
            f01 = __ldg(&tables[(hx0 ^ hy1 ^ se) & mask]);
            f11 = __ldg(&tables[(hx1 ^ hy1 ^ se) & mask]);
        }

        const float w00 = gx * gy, w10 = fx * gy;
        const float w01 = gx * fy, w11 = fx * fy;
        const float ex = w00 * f00.x + w10 * f10.x + w01 * f01.x + w11 * f11.x;
        const float ey = w00 * f00.y + w10 * f10.y + w01 * f01.y + w11 * f11.y;

        outb[(size_t)(2 * l)     * (size_t)HW] = ex;
        outb[(size_t)(2 * l + 1) * (size_t)HW] = ey;
    }
}

// ---------------------------------------------------------------------------
// Generic fallback (round-1 kernel): one thread per pixel.
// ---------------------------------------------------------------------------
template <int LFIX, bool POW2>
__global__ void __launch_bounds__(256)
hashenc_kernel(const float* __restrict__ x0,
               const float* __restrict__ y0,
               const float2* __restrict__ tables,
               const unsigned int* __restrict__ seeds,
               const float* __restrict__ levelN,
               const int* __restrict__ tile_ptr,
               float* __restrict__ out,
               int B, int H, int Lrt,
               unsigned int T, unsigned int mask)
{
    const int L = (LFIX > 0) ? LFIX : Lrt;

    __shared__ float s_scale[64];
    __shared__ unsigned int s_seed[64];
    if (threadIdx.x < L) {
        float tf = read_scalar_as_float(tile_ptr);
        s_scale[threadIdx.x] = levelN[threadIdx.x] / tf;
        s_seed[threadIdx.x]  = seeds[threadIdx.x];
    }
    __syncthreads();

    const int HW = H * H;
    const long long total = (long long)B * HW;
    const long long tid = (long long)blockIdx.x * blockDim.x + threadIdx.x;
    if (tid >= total) return;

    const int pix = (int)(tid % HW);
    const int b   = (int)(tid / HW);
    const int w   = pix % H;
    const int h   = pix / H;

    const float px = (float)w + x0[b];
    const float py = (float)h + y0[b];

    float* outb = out + (size_t)b * (size_t)(2 * L) * (size_t)HW + pix;

    #pragma unroll
    for (int l = 0; l < L; l++) {
        const float sc = s_scale[l];
        const float xn = px * sc;
        const float yn = py * sc;
        const float fx0f = floorf(xn);
        const float fy0f = floorf(yn);
        const int ix0 = (int)fx0f;
        const int iy0 = (int)fy0f;
        const float fx = xn - fx0f;
        const float fy = yn - fy0f;

        const unsigned int se  = s_seed[l];
        const unsigned int hx0 = (unsigned int)ix0 * HASH_P1;
        const unsigned int hx1 = hx0 + HASH_P1;
        const unsigned int hy0 = (unsigned int)iy0 * HASH_P2;
        const unsigned int hy1 = hy0 + HASH_P2;

        unsigned int i00, i10, i01, i11;
        if (POW2) {
            i00 = (hx0 ^ hy0 ^ se) & mask;
            i10 = (hx1 ^ hy0 ^ se) & mask;
            i01 = (hx0 ^ hy1 ^ se) & mask;
            i11 = (hx1 ^ hy1 ^ se) & mask;
        } else {
            i00 = (hx0 ^ hy0 ^ se) % T;
            i10 = (hx1 ^ hy0 ^ se) % T;
            i01 = (hx0 ^ hy1 ^ se) % T;
            i11 = (hx1 ^ hy1 ^ se) % T;
        }

        const float2 f00 = __ldg(&tables[i00]);
        const float2 f10 = __ldg(&tables[i10]);
        const float2 f01 = __ldg(&tables[i01]);
        const float2 f11 = __ldg(&tables[i11]);

        const float gx = 1.0f - fx;
        const float gy = 1.0f - fy;
        const float w00 = gx * gy;
        const float w10 = fx * gy;
        const float w01 = gx * fy;
        const float w11 = fx * fy;

        const float ex = w00 * f00.x + w10 * f10.x + w01 * f01.x + w11 * f11.x;
        const float ey = w00 * f00.y + w10 * f10.y + w01 * f01.y + w11 * f11.y;

        outb[(size_t)(2 * l)     * (size_t)HW] = ex;
        outb[(size_t)(2 * l + 1) * (size_t)HW] = ey;
    }
}

extern "C" void kernel_launch(void* const* d_in, const int* in_sizes, int n_in,
                              void* d_out, int out_size)
{
    const float*        x0     = (const float*)d_in[0];
    const float*        y0     = (const float*)d_in[1];
    const float2*       tables = (const float2*)d_in[2];
    const unsigned int* seeds  = (const unsigned int*)d_in[3];
    const float*        levelN = (const float*)d_in[4];
    const int*          tile   = (const int*)d_in[6];   // complete_tile_size scalar
    float*              out    = (float*)d_out;

    const int B = in_sizes[0];
    const int L = in_sizes[3];
    const unsigned int T = (unsigned int)(in_sizes[2] / 2);   // FEAT_DIM = 2

    const long long hw = (long long)out_size / ((long long)B * 2LL * (long long)L);
    int H = (int)(sqrt((double)hw) + 0.5);

    const bool pow2 = (T & (T - 1)) == 0;
    const unsigned int mask = T - 1;

    if (pow2 && L <= 16 && (H % TW) == 0 && B <= 65535) {
        dim3 grid(H / TW, H / TH, B);
        hashenc_tiled<<<grid, 256>>>(x0, y0, tables, seeds, levelN, tile,
                                     out, H, L, mask);
        return;
    }

    const long long total = (long long)B * H * H;
    const int threads = 256;
    const int blocks = (int)((total + threads - 1) / threads);

    if (L == 16) {
        if (pow2)
            hashenc_kernel<16, true><<<blocks, threads>>>(x0, y0, tables, seeds, levelN,
                                                          tile, out, B, H, L, T, mask);
        else
            hashenc_kernel<16, false><<<blocks, threads>>>(x0, y0, tables, seeds, levelN,
                                                           tile, out, B, H, L, T, mask);
    } else {
        if (pow2)
            hashenc_kernel<0, true><<<blocks, threads>>>(x0, y0, tables, seeds, levelN,
                                                         tile, out, B, H, L, T, mask);
        else
            hashenc_kernel<0, false><<<blocks, threads>>>(x0, y0, tables, seeds, levelN,
                                                          tile, out, B, H, L, T, mask);
    }
}

// round 6
// speedup vs baseline: 1.0341x; 1.0341x over previous
#include <cuda_runtime.h>
#include <math.h>

// LIANetLight hash-grid encoder.
// Inputs (metadata order):
//  0: x0      float32 [B]
//  1: y0      float32 [B]
//  2: tables  float32 [T, 2]
//  3: seeds   uint32  [L]
//  4: level_N float32 [L]
//  5: memorized_crop_size (scalar)
//  6: complete_tile_size  (scalar)
// Output: float32 [B, L*2, H, W]

#define HASH_P1 2654435761u
#define HASH_P2 805459861u
#define TW 32
#define TH 8
#define STAGE_TOT 1200   // float2 entries (9.6 KB): greedily stages l0..l11

// Read a scalar that may have been stored as int32 or float32.
__device__ __forceinline__ float read_scalar_as_float(const int* p) {
    int v = *p;
    if (v > 0 && v < (1 << 24)) return (float)v;
    return __int_as_float(v);
}

// ---------------------------------------------------------------------------
// Single-barrier staged kernel.
// CTA = 32x8 pixel tile, 256 threads, 1 pixel/thread; warp = one row
// (coalesced stores). Pass 1 cooperatively fills ALL staged levels' cell
// rectangles into one smem arena (no barriers between levels -> deep MLP);
// one __syncthreads(); Pass 2 interpolates every level, staged levels from
// smem, fine levels direct from L2.
// Staging rule (uniform across grid, recomputed identically in both passes):
// greedy by level while worst-case cells fit in STAGE_TOT.
// Requires: H % 32 == 0, H % 8 == 0, T power of two, L <= 16.
// ---------------------------------------------------------------------------
__global__ void __launch_bounds__(256)
hashenc_staged(const float* __restrict__ x0,
               const float* __restrict__ y0,
               const float2* __restrict__ tables,
               const unsigned int* __restrict__ seeds,
               const float* __restrict__ levelN,
               const int* __restrict__ tile_ptr,
               float* __restrict__ out,
               int H, int L, unsigned int mask)
{
    __shared__ float2 stage[STAGE_TOT];
    __shared__ float s_scale[16];
    __shared__ unsigned int s_seed[16];
    __shared__ float s_org[2];

    const int tid = threadIdx.x;
    const int b = blockIdx.z;

    if (tid < L) {
        float tf = read_scalar_as_float(tile_ptr);
        s_scale[tid] = levelN[tid] / tf;
        s_seed[tid]  = seeds[tid];
    }
    if (tid == 0) { s_org[0] = x0[b]; s_org[1] = y0[b]; }
    __syncthreads();

    const float ox = s_org[0];
    const float oy = s_org[1];
    const int tilex = blockIdx.x * TW;
    const int tiley = blockIdx.y * TH;
    const int tx = tid & 31;          // 0..31
    const int ty = tid >> 5;          // 0..7
    const int HW = H * H;
    const float px = (float)(tilex + tx) + ox;
    const float py = (float)(tiley + ty) + oy;

    // ---------------- Pass 1: fill all staged levels (no inner barriers) ----
    {
        int off = 0;
        for (int l = 0; l < L; l++) {
            const float sc = s_scale[l];
            // worst-case cell rectangle for ANY 32x8 tile at this scale
            const int nxw = (int)floorf((float)(TW - 1) * sc) + 3;
            const int nyw = (int)floorf((float)(TH - 1) * sc) + 3;
            const int ncwc = nxw * nyw;
            if (off + ncwc > STAGE_TOT) break;   // ncwc monotone -> all later fail

            const unsigned int se = s_seed[l];
            const int ixmin = (int)floorf(((float)tilex + ox) * sc);
            const int iymin = (int)floorf(((float)tiley + oy) * sc);
            const int nx = (int)floorf(((float)(tilex + TW - 1) + ox) * sc) - ixmin + 2;
            const int ny = (int)floorf(((float)(tiley + TH - 1) + oy) * sc) - iymin + 2;
            const int ncells = nx * ny;

            for (int i = tid; i < ncells; i += 256) {
                const int cy = i / nx;
                const int cx = i - cy * nx;
                const unsigned int h = ((unsigned int)(ixmin + cx) * HASH_P1)
                                     ^ ((unsigned int)(iymin + cy) * HASH_P2) ^ se;
                stage[off + i] = __ldg(&tables[h & mask]);
            }
            off += ncwc;
        }
    }
    __syncthreads();   // the only stage barrier

    // ---------------- Pass 2: interpolate all levels ------------------------
    float* outb = out + (size_t)b * (size_t)(2 * L) * (size_t)HW
                      + (size_t)(tiley + ty) * (size_t)H + (tilex + tx);

    int off = 0;
    for (int l = 0; l < L; l++) {
        const float sc        = s_scale[l];
        const unsigned int se = s_seed[l];

        const float xn  = px * sc;
        const float fxf = floorf(xn);
        const float fx  = xn - fxf;
        const int ix0   = (int)fxf;
        const float gx  = 1.0f - fx;

        const float yn  = py * sc;
        const float fyf = floorf(yn);
        const float fy  = yn - fyf;
        const int iy0   = (int)fyf;
        const float gy  = 1.0f - fy;

        const int nxw = (int)floorf((float)(TW - 1) * sc) + 3;
        const int nyw = (int)floorf((float)(TH - 1) * sc) + 3;
        const int ncwc = nxw * nyw;
        const bool staged = (off + ncwc <= STAGE_TOT);

        float2 f00, f10, f01, f11;
        if (staged) {
            const int ixmin = (int)floorf(((float)tilex + ox) * sc);
            const int iymin = (int)floorf(((float)tiley + oy) * sc);
            const int nx = (int)floorf(((float)(tilex + TW - 1) + ox) * sc) - ixmin + 2;
            const int base0 = off + (iy0 - iymin) * nx + (ix0 - ixmin);
            f00 = stage[base0];
            f10 = stage[base0 + 1];
            f01 = stage[base0 + nx];
            f11 = stage[base0 + nx + 1];
            off += ncwc;
        } else {
            const unsigned int hx0 = (unsigned int)ix0 * HASH_P1;
            const unsigned int hx1 = hx0 + HASH_P1;   // (ix0+1)*P1 mod 2^32
            const unsigned int hy0 = (unsigned int)iy0 * HASH_P2;
            const unsigned int hy1 = hy0 + HASH_P2;
            f00 = __ldg(&tables[(hx0 ^ hy0 ^ se) & mask]);
            f10 = __ldg(&tables[(hx1 ^ hy0 ^ se) & mask]);
            f01 = __ldg(&tables[(hx0 ^ hy1 ^ se) & mask]);
            f11 = __ldg(&tables[(hx1 ^ hy1 ^ se) & mask]);
        }

        const float w00 = gx * gy, w10 = fx * gy;
        const float w01 = gx * fy, w11 = fx * fy;
        const float ex = w00 * f00.x + w10 * f10.x + w01 * f01.x + w11 * f11.x;
        const float ey = w00 * f00.y + w10 * f10.y + w01 * f01.y + w11 * f11.y;

        outb[(size_t)(2 * l)     * (size_t)HW] = ex;
        outb[(size_t)(2 * l + 1) * (size_t)HW] = ey;
    }
}

// ---------------------------------------------------------------------------
// Generic fallback (round-1 kernel): one thread per pixel.
// ---------------------------------------------------------------------------
template <int LFIX, bool POW2>
__global__ void __launch_bounds__(256)
hashenc_kernel(const float* __restrict__ x0,
               const float* __restrict__ y0,
               const float2* __restrict__ tables,
               const unsigned int* __restrict__ seeds,
               const float* __restrict__ levelN,
               const int* __restrict__ tile_ptr,
               float* __restrict__ out,
               int B, int H, int Lrt,
               unsigned int T, unsigned int mask)
{
    const int L = (LFIX > 0) ? LFIX : Lrt;

    __shared__ float s_scale[64];
    __shared__ unsigned int s_seed[64];
    if (threadIdx.x < L) {
        float tf = read_scalar_as_float(tile_ptr);
        s_scale[threadIdx.x] = levelN[threadIdx.x] / tf;
        s_seed[threadIdx.x]  = seeds[threadIdx.x];
    }
    __syncthreads();

    const int HW = H * H;
    const long long total = (long long)B * HW;
    const long long tid = (long long)blockIdx.x * blockDim.x + threadIdx.x;
    if (tid >= total) return;

    const int pix = (int)(tid % HW);
    const int b   = (int)(tid / HW);
    const int w   = pix % H;
    const int h   = pix / H;

    const float px = (float)w + x0[b];
    const float py = (float)h + y0[b];

    float* outb = out + (size_t)b * (size_t)(2 * L) * (size_t)HW + pix;

    #pragma unroll
    for (int l = 0; l < L; l++) {
        const float sc = s_scale[l];
        const float xn = px * sc;
        const float yn = py * sc;
        const float fx0f = floorf(xn);
        const float fy0f = floorf(yn);
        const int ix0 = (int)fx0f;
        const int iy0 = (int)fy0f;
        const float fx = xn - fx0f;
        const float fy = yn - fy0f;

        const unsigned int se  = s_seed[l];
        const unsigned int hx0 = (unsigned int)ix0 * HASH_P1;
        const unsigned int hx1 = hx0 + HASH_P1;
        const unsigned int hy0 = (unsigned int)iy0 * HASH_P2;
        const unsigned int hy1 = hy0 + HASH_P2;

        unsigned int i00, i10, i01, i11;
        if (POW2) {
            i00 = (hx0 ^ hy0 ^ se) & mask;
            i10 = (hx1 ^ hy0 ^ se) & mask;
            i01 = (hx0 ^ hy1 ^ se) & mask;
            i11 = (hx1 ^ hy1 ^ se) & mask;
        } else {
            i00 = (hx0 ^ hy0 ^ se) % T;
            i10 = (hx1 ^ hy0 ^ se) % T;
            i01 = (hx0 ^ hy1 ^ se) % T;
            i11 = (hx1 ^ hy1 ^ se) % T;
        }

        const float2 f00 = __ldg(&tables[i00]);
        const float2 f10 = __ldg(&tables[i10]);
        const float2 f01 = __ldg(&tables[i01]);
        const float2 f11 = __ldg(&tables[i11]);

        const float gx = 1.0f - fx;
        const float gy = 1.0f - fy;
        const float w00 = gx * gy;
        const float w10 = fx * gy;
        const float w01 = gx * fy;
        const float w11 = fx * fy;

        const float ex = w00 * f00.x + w10 * f10.x + w01 * f01.x + w11 * f11.x;
        const float ey = w00 * f00.y + w10 * f10.y + w01 * f01.y + w11 * f11.y;

        outb[(size_t)(2 * l)     * (size_t)HW] = ex;
        outb[(size_t)(2 * l + 1) * (size_t)HW] = ey;
    }
}

extern "C" void kernel_launch(void* const* d_in, const int* in_sizes, int n_in,
                              void* d_out, int out_size)
{
    const float*        x0     = (const float*)d_in[0];
    const float*        y0     = (const float*)d_in[1];
    const float2*       tables = (const float2*)d_in[2];
    const unsigned int* seeds  = (const unsigned int*)d_in[3];
    const float*        levelN = (const float*)d_in[4];
    const int*          tile   = (const int*)d_in[6];   // complete_tile_size scalar
    float*              out    = (float*)d_out;

    const int B = in_sizes[0];
    const int L = in_sizes[3];
    const unsigned int T = (unsigned int)(in_sizes[2] / 2);   // FEAT_DIM = 2

    const long long hw = (long long)out_size / ((long long)B * 2LL * (long long)L);
    int H = (int)(sqrt((double)hw) + 0.5);

    const bool pow2 = (T & (T - 1)) == 0;
    const unsigned int mask = T - 1;

    if (pow2 && L <= 16 && (H % TW) == 0 && (H % TH) == 0 && B <= 65535) {
        dim3 grid(H / TW, H / TH, B);
        hashenc_staged<<<grid, 256>>>(x0, y0, tables, seeds, levelN, tile,
                                      out, H, L, mask);
        return;
    }

    const long long total = (long long)B * H * H;
    const int threads = 256;
    const int blocks = (int)((total + threads - 1) / threads);

    if (L == 16) {
        if (pow2)
            hashenc_kernel<16, true><<<blocks, threads>>>(x0, y0, tables, seeds, levelN,
                                                          tile, out, B, H, L, T, mask);
        else
            hashenc_kernel<16, false><<<blocks, threads>>>(x0, y0, tables, seeds, levelN,
                                                           tile, out, B, H, L, T, mask);
    } else {
        if (pow2)
            hashenc_kernel<0, true><<<blocks, threads>>>(x0, y0, tables, seeds, levelN,
                                                         tile, out, B, H, L, T, mask);
        else
            hashenc_kernel<0, false><<<blocks, threads>>>(x0, y0, tables, seeds, levelN,
                                                          tile, out, B, H, L, T, mask);
    }
}

// round 7
// speedup vs baseline: 1.0356x; 1.0015x over previous
#include <cuda_runtime.h>
#include <math.h>

// LIANetLight hash-grid encoder.
// Inputs (metadata order):
//  0: x0      float32 [B]
//  1: y0      float32 [B]
//  2: tables  float32 [T, 2]
//  3: seeds   uint32  [L]
//  4: level_N float32 [L]
//  5: memorized_crop_size (scalar)
//  6: complete_tile_size  (scalar)
// Output: float32 [B, L*2, H, W]

#define HASH_P1 2654435761u
#define HASH_P2 805459861u
#define TW 32
#define TH 8
#define STAGE_TOT 1200   // float2 entries (9.6 KB)
#define NCWC_MAX  600    // per-level worst-case cap (stages l0..l11 for std cfg)

__device__ __forceinline__ float read_scalar_as_float(const int* p) {
    int v = *p;
    if (v > 0 && v < (1 << 24)) return (float)v;
    return __int_as_float(v);
}

// ---------------------------------------------------------------------------
// Staged kernel, latency-hiding order:
//   init meta (16 threads) -> barrier -> fill stage (no wait) ->
//   FINE levels direct (hides fill latency) -> barrier -> staged levels.
// CTA = 32x8 tile, 256 threads, 1 px/thread; warp = row (coalesced stores).
// Staging rule: greedy prefix of levels while worst-case cell rect <= NCWC_MAX
// and cumulative fits STAGE_TOT (deterministic, same everywhere).
// Requires: H % 32 == 0, H % 8 == 0, T power of two, L <= 16.
// ---------------------------------------------------------------------------
__global__ void __launch_bounds__(256)
hashenc_staged(const float* __restrict__ x0,
               const float* __restrict__ y0,
               const float2* __restrict__ tables,
               const unsigned int* __restrict__ seeds,
               const float* __restrict__ levelN,
               const int* __restrict__ tile_ptr,
               float* __restrict__ out,
               int H, int L, unsigned int mask)
{
    __shared__ float2 stage[STAGE_TOT];
    __shared__ float s_scale[16];
    __shared__ unsigned int s_seed[16];
    __shared__ int s_off[16], s_nx[16], s_ncells[16], s_ixmin[16], s_iymin[16];
    __shared__ float s_org[2];

    const int tid = threadIdx.x;
    const int b = blockIdx.z;
    const int tilex = blockIdx.x * TW;
    const int tiley = blockIdx.y * TH;

    // ---- init: per-level metadata, once per CTA ----
    if (tid < L) {
        const float tf = read_scalar_as_float(tile_ptr);
        const float sc = levelN[tid] / tf;
        s_scale[tid] = sc;
        s_seed[tid]  = seeds[tid];
        const float oxl = x0[b];
        const float oyl = y0[b];
        if (tid == 0) { s_org[0] = oxl; s_org[1] = oyl; }

        // greedy prefix: staged iff all levels <= tid pass the caps
        int off = 0, myoff = -1;
        for (int l = 0; l <= tid; l++) {
            const float scl = levelN[l] / tf;
            const int nxw = (int)floorf((float)(TW - 1) * scl) + 3;
            const int nyw = (int)floorf((float)(TH - 1) * scl) + 3;
            const int ncwc = nxw * nyw;
            if (ncwc > NCWC_MAX || off + ncwc > STAGE_TOT) break;  // prefix ends
            if (l == tid) myoff = off;
            off += ncwc;
        }
        s_off[tid] = myoff;
        if (myoff >= 0) {
            const int ixmin = (int)floorf(((float)tilex + oxl) * sc);
            const int iymin = (int)floorf(((float)tiley + oyl) * sc);
            const int nx = (int)floorf(((float)(tilex + TW - 1) + oxl) * sc) - ixmin + 2;
            const int ny = (int)floorf(((float)(tiley + TH - 1) + oyl) * sc) - iymin + 2;
            s_ixmin[tid] = ixmin;
            s_iymin[tid] = iymin;
            s_nx[tid]    = nx;
            s_ncells[tid] = nx * ny;
        }
    }
    __syncthreads();

    const float ox = s_org[0];
    const float oy = s_org[1];
    const int tx = tid & 31;
    const int ty = tid >> 5;
    const int HW = H * H;
    const float px = (float)(tilex + tx) + ox;
    const float py = (float)(tiley + ty) + oy;

    // ---- pass 1: fill all staged levels (no waiting) ----
    int nstaged = 0;
    while (nstaged < L && s_off[nstaged] >= 0) nstaged++;

    for (int l = 0; l < nstaged; l++) {
        const int off = s_off[l];
        const int nx = s_nx[l];
        const int ncells = s_ncells[l];
        const int ixmin = s_ixmin[l];
        const int iymin = s_iymin[l];
        const unsigned int se = s_seed[l];
        for (int i = tid; i < ncells; i += 256) {
            const int cy = i / nx;
            const int cx = i - cy * nx;
            const unsigned int h = ((unsigned int)(ixmin + cx) * HASH_P1)
                                 ^ ((unsigned int)(iymin + cy) * HASH_P2) ^ se;
            stage[off + i] = __ldg(&tables[h & mask]);
        }
    }

    float* outb = out + (size_t)b * (size_t)(2 * L) * (size_t)HW
                      + (size_t)(tiley + ty) * (size_t)H + (tilex + tx);

    // ---- fine levels, direct, software-pipelined (runs under fill latency) --
    if (nstaged < L) {
        float fxA, fyA;
        float2 a00, a10, a01, a11;
        {
            const float sc = s_scale[nstaged];
            const unsigned int se = s_seed[nstaged];
            const float xn = px * sc;
            const float fxf = floorf(xn);
            fxA = xn - fxf;
            const float yn = py * sc;
            const float fyf = floorf(yn);
            fyA = yn - fyf;
            const unsigned int hx0 = (unsigned int)(int)fxf * HASH_P1;
            const unsigned int hx1 = hx0 + HASH_P1;
            const unsigned int hy0 = (unsigned int)(int)fyf * HASH_P2;
            const unsigned int hy1 = hy0 + HASH_P2;
            a00 = __ldg(&tables[(hx0 ^ hy0 ^ se) & mask]);
            a10 = __ldg(&tables[(hx1 ^ hy0 ^ se) & mask]);
            a01 = __ldg(&tables[(hx0 ^ hy1 ^ se) & mask]);
            a11 = __ldg(&tables[(hx1 ^ hy1 ^ se) & mask]);
        }
        for (int l = nstaged; l < L; l++) {
            const float fx = fxA, fy = fyA;
            const float2 f00 = a00, f10 = a10, f01 = a01, f11 = a11;
            if (l + 1 < L) {   // prefetch next fine level
                const float sc = s_scale[l + 1];
                const unsigned int se = s_seed[l + 1];
                const float xn = px * sc;
                const float fxf = floorf(xn);
                fxA = xn - fxf;
                const float yn = py * sc;
                const float fyf = floorf(yn);
                fyA = yn - fyf;
                const unsigned int hx0 = (unsigned int)(int)fxf * HASH_P1;
                const unsigned int hx1 = hx0 + HASH_P1;
                const unsigned int hy0 = (unsigned int)(int)fyf * HASH_P2;
                const unsigned int hy1 = hy0 + HASH_P2;
                a00 = __ldg(&tables[(hx0 ^ hy0 ^ se) & mask]);
                a10 = __ldg(&tables[(hx1 ^ hy0 ^ se) & mask]);
                a01 = __ldg(&tables[(hx0 ^ hy1 ^ se) & mask]);
                a11 = __ldg(&tables[(hx1 ^ hy1 ^ se) & mask]);
            }
            const float gx = 1.0f - fx, gy = 1.0f - fy;
            const float w00 = gx * gy, w10 = fx * gy;
            const float w01 = gx * fy, w11 = fx * fy;
            const float ex = w00 * f00.x + w10 * f10.x + w01 * f01.x + w11 * f11.x;
            const float ey = w00 * f00.y + w10 * f10.y + w01 * f01.y + w11 * f11.y;
            outb[(size_t)(2 * l)     * (size_t)HW] = ex;
            outb[(size_t)(2 * l + 1) * (size_t)HW] = ey;
        }
    }

    __syncthreads();   // stage[] now complete (fill latency hidden above)

    // ---- staged levels from shared memory ----
    for (int l = 0; l < nstaged; l++) {
        const float sc = s_scale[l];
        const float xn = px * sc;
        const float fxf = floorf(xn);
        const float fx = xn - fxf;
        const float yn = py * sc;
        const float fyf = floorf(yn);
        const float fy = yn - fyf;

        const int nx = s_nx[l];
        const int base0 = s_off[l] + ((int)fyf - s_iymin[l]) * nx
                                   + ((int)fxf - s_ixmin[l]);
        const float2 f00 = stage[base0];
        const float2 f10 = stage[base0 + 1];
        const float2 f01 = stage[base0 + nx];
        const float2 f11 = stage[base0 + nx + 1];

        const float gx = 1.0f - fx, gy = 1.0f - fy;
        const float w00 = gx * gy, w10 = fx * gy;
        const float w01 = gx * fy, w11 = fx * fy;
        const float ex = w00 * f00.x + w10 * f10.x + w01 * f01.x + w11 * f11.x;
        const float ey = w00 * f00.y + w10 * f10.y + w01 * f01.y + w11 * f11.y;

        outb[(size_t)(2 * l)     * (size_t)HW] = ex;
        outb[(size_t)(2 * l + 1) * (size_t)HW] = ey;
    }
}

// ---------------------------------------------------------------------------
// Generic fallback (round-1 kernel): one thread per pixel.
// ---------------------------------------------------------------------------
template <int LFIX, bool POW2>
__global__ void __launch_bounds__(256)
hashenc_kernel(const float* __restrict__ x0,
               const float* __restrict__ y0,
               const float2* __restrict__ tables,
               const unsigned int* __restrict__ seeds,
               const float* __restrict__ levelN,
               const int* __restrict__ tile_ptr,
               float* __restrict__ out,
               int B, int H, int Lrt,
               unsigned int T, unsigned int mask)
{
    const int L = (LFIX > 0) ? LFIX : Lrt;

    __shared__ float s_scale[64];
    __shared__ unsigned int s_seed[64];
    if (threadIdx.x < L) {
        float tf = read_scalar_as_float(tile_ptr);
        s_scale[threadIdx.x] = levelN[threadIdx.x] / tf;
        s_seed[threadIdx.x]  = seeds[threadIdx.x];
    }
    __syncthreads();

    const int HW = H * H;
    const long long total = (long long)B * HW;
    const long long tid = (long long)blockIdx.x * blockDim.x + threadIdx.x;
    if (tid >= total) return;

    const int pix = (int)(tid % HW);
    const int b   = (int)(tid / HW);
    const int w   = pix % H;
    const int h   = pix / H;

    const float px = (float)w + x0[b];
    const float py = (float)h + y0[b];

    float* outb = out + (size_t)b * (size_t)(2 * L) * (size_t)HW + pix;

    #pragma unroll
    for (int l = 0; l < L; l++) {
        const float sc = s_scale[l];
        const float xn = px * sc;
        const float yn = py * sc;
        const float fx0f = floorf(xn);
        const float fy0f = floorf(yn);
        const int ix0 = (int)fx0f;
        const int iy0 = (int)fy0f;
        const float fx = xn - fx0f;
        const float fy = yn - fy0f;

        const unsigned int se  = s_seed[l];
        const unsigned int hx0 = (unsigned int)ix0 * HASH_P1;
        const unsigned int hx1 = hx0 + HASH_P1;
        const unsigned int hy0 = (unsigned int)iy0 * HASH_P2;
        const unsigned int hy1 = hy0 + HASH_P2;

        unsigned int i00, i10, i01, i11;
        if (POW2) {
            i00 = (hx0 ^ hy0 ^ se) & mask;
            i10 = (hx1 ^ hy0 ^ se) & mask;
            i01 = (hx0 ^ hy1 ^ se) & mask;
            i11 = (hx1 ^ hy1 ^ se) & mask;
        } else {
            i00 = (hx0 ^ hy0 ^ se) % T;
            i10 = (hx1 ^ hy0 ^ se) % T;
            i01 = (hx0 ^ hy1 ^ se) % T;
            i11 = (hx1 ^ hy1 ^ se) % T;
        }

        const float2 f00 = __ldg(&tables[i00]);
        const float2 f10 = __ldg(&tables[i10]);
        const float2 f01 = __ldg(&tables[i01]);
        const float2 f11 = __ldg(&tables[i11]);

        const float gx = 1.0f - fx;
        const float gy = 1.0f - fy;
        const float w00 = gx * gy;
        const float w10 = fx * gy;
        const float w01 = gx * fy;
        const float w11 = fx * fy;

        const float ex = w00 * f00.x + w10 * f10.x + w01 * f01.x + w11 * f11.x;
        const float ey = w00 * f00.y + w10 * f10.y + w01 * f01.y + w11 * f11.y;

        outb[(size_t)(2 * l)     * (size_t)HW] = ex;
        outb[(size_t)(2 * l + 1) * (size_t)HW] = ey;
    }
}

extern "C" void kernel_launch(void* const* d_in, const int* in_sizes, int n_in,
                              void* d_out, int out_size)
{
    const float*        x0     = (const float*)d_in[0];
    const float*        y0     = (const float*)d_in[1];
    const float2*       tables = (const float2*)d_in[2];
    const unsigned int* seeds  = (const unsigned int*)d_in[3];
    const float*        levelN = (const float*)d_in[4];
    const int*          tile   = (const int*)d_in[6];   // complete_tile_size scalar
    float*              out    = (float*)d_out;

    const int B = in_sizes[0];
    const int L = in_sizes[3];
    const unsigned int T = (unsigned int)(in_sizes[2] / 2);   // FEAT_DIM = 2

    const long long hw = (long long)out_size / ((long long)B * 2LL * (long long)L);
    int H = (int)(sqrt((double)hw) + 0.5);

    const bool pow2 = (T & (T - 1)) == 0;
    const unsigned int mask = T - 1;

    if (pow2 && L <= 16 && (H % TW) == 0 && (H % TH) == 0 && B <= 65535) {
        dim3 grid(H / TW, H / TH, B);
        hashenc_staged<<<grid, 256>>>(x0, y0, tables, seeds, levelN, tile,
                                      out, H, L, mask);
        return;
    }

    const long long total = (long long)B * H * H;
    const int threads = 256;
    const int blocks = (int)((total + threads - 1) / threads);

    if (L == 16) {
        if (pow2)
            hashenc_kernel<16, true><<<blocks, threads>>>(x0, y0, tables, seeds, levelN,
                                                          tile, out, B, H, L, T, mask);
        else
            hashenc_kernel<16, false><<<blocks, threads>>>(x0, y0, tables, seeds, levelN,
                                                           tile, out, B, H, L, T, mask);
    } else {
        if (pow2)
            hashenc_kernel<0, true><<<blocks, threads>>>(x0, y0, tables, seeds, levelN,
                                                         tile, out, B, H, L, T, mask);
        else
            hashenc_kernel<0, false><<<blocks, threads>>>(x0, y0, tables, seeds, levelN,
                                                          tile, out, B, H, L, T, mask);
    }
}